// round 1
// baseline (speedup 1.0000x reference)
#include <cuda_runtime.h>
#include <math.h>

#define CC 256   // channels
#define BB 512   // batch / segments
#define LL 256   // nodes per segment
#define RR 8     // bank rows

// ---- scratch (device globals; no allocation allowed) ----
__device__ float g_h[BB * CC];              // LSTM hidden (== q)
__device__ float g_c[BB * CC];              // LSTM cell
__device__ float g_part[3][BB * 4 * CC];    // split-K GEMM partials

// ============================================================
// Kernel 1: a_sit[b,c] = sum_l bank_s[b,index,l] * x[b*L+l, c]
// Also zero-inits cell state. One CTA per segment, 256 threads.
// ============================================================
__global__ void asit_kernel(const float* __restrict__ x,
                            const float* __restrict__ bank_s,
                            const int* __restrict__ index_p) {
    int b = blockIdx.x;
    int c = threadIdx.x;
    __shared__ float s[LL];
    int idx = *index_p;
    s[c] = bank_s[((size_t)b * RR + idx) * LL + c];   // c < 256 == LL
    __syncthreads();
    const float* xb = x + (size_t)b * LL * CC;
    float acc = 0.f;
#pragma unroll 8
    for (int l = 0; l < LL; l++)
        acc = fmaf(s[l], xb[(size_t)l * CC + c], acc);
    g_h[b * CC + c] = acc;
    g_c[b * CC + c] = 0.f;
}

// ============================================================
// Kernel 2: split-K gates GEMM.
// gates[m][n] = sum_k qstar[m][k] w_ih[n][k] + sum_k h[m][k] w_hh[n][k]
// Slice 0: qstar cols [0,256)  vs w_ih cols [0,256)
// Slice 1: qstar cols [256,512) vs w_ih cols [256,512)
// Slice 2: h (256)             vs w_hh
// Tile 64x64, 256 threads, 4x4 micro-tile, k-tile 16, K=256 per slice.
// grid = (16 ntilesN, 8 ntilesM, 3 slices) = 384 CTAs.
// Partials stored to g_part (no atomics -> deterministic).
// ============================================================
__global__ void gemm_slice_kernel(const float* __restrict__ qs,
                                  const float* __restrict__ w_ih,
                                  const float* __restrict__ w_hh) {
    int s = blockIdx.z;
    const float* A;
    const float* W;
    int lda, ldw;
    if (s == 0)      { A = qs;        lda = 2 * CC; W = w_ih;       ldw = 2 * CC; }
    else if (s == 1) { A = qs + CC;   lda = 2 * CC; W = w_ih + CC;  ldw = 2 * CC; }
    else             { A = g_h;       lda = CC;     W = w_hh;       ldw = CC;     }

    const int m0 = blockIdx.y * 64;
    const int n0 = blockIdx.x * 64;
    __shared__ float As[16][64];   // k-major
    __shared__ float Ws[16][64];   // k-major

    const int tid = threadIdx.x;
    const int tx = tid & 15, ty = tid >> 4;
    const int lrow = tid >> 2;          // 0..63
    const int lk4  = (tid & 3) * 4;     // 0,4,8,12

    float acc[4][4];
#pragma unroll
    for (int i = 0; i < 4; i++)
#pragma unroll
        for (int j = 0; j < 4; j++) acc[i][j] = 0.f;

    for (int k0 = 0; k0 < 256; k0 += 16) {
        float4 av = *(const float4*)(A + (size_t)(m0 + lrow) * lda + k0 + lk4);
        float4 wv = *(const float4*)(W + (size_t)(n0 + lrow) * ldw + k0 + lk4);
        __syncthreads();  // protect previous iteration's reads
        As[lk4 + 0][lrow] = av.x; As[lk4 + 1][lrow] = av.y;
        As[lk4 + 2][lrow] = av.z; As[lk4 + 3][lrow] = av.w;
        Ws[lk4 + 0][lrow] = wv.x; Ws[lk4 + 1][lrow] = wv.y;
        Ws[lk4 + 2][lrow] = wv.z; Ws[lk4 + 3][lrow] = wv.w;
        __syncthreads();
#pragma unroll
        for (int kk = 0; kk < 16; kk++) {
            float4 a = *(const float4*)&As[kk][ty * 4];
            float4 b = *(const float4*)&Ws[kk][tx * 4];
            float aa[4] = {a.x, a.y, a.z, a.w};
            float bb[4] = {b.x, b.y, b.z, b.w};
#pragma unroll
            for (int i = 0; i < 4; i++)
#pragma unroll
                for (int j = 0; j < 4; j++)
                    acc[i][j] = fmaf(aa[i], bb[j], acc[i][j]);
        }
    }

    float* outp = &g_part[s][0];
#pragma unroll
    for (int i = 0; i < 4; i++) {
        float4 r = make_float4(acc[i][0], acc[i][1], acc[i][2], acc[i][3]);
        *(float4*)(outp + (size_t)(m0 + ty * 4 + i) * (4 * CC) + n0 + tx * 4) = r;
    }
}

// ============================================================
// Kernel 3: LSTM elementwise. Sums split-K partials + biases,
// gate order i,f,g,o. Writes h into g_h and the q-half of d_out.
// ============================================================
__device__ __forceinline__ float sigf(float v) { return 1.f / (1.f + expf(-v)); }

__global__ void lstm_elem_kernel(const float* __restrict__ b_ih,
                                 const float* __restrict__ b_hh,
                                 float* __restrict__ out) {
    int i = blockIdx.x * blockDim.x + threadIdx.x;   // 0 .. B*C-1
    int b = i >> 8;
    int ch = i & 255;
    size_t base = (size_t)b * (4 * CC);

    float gate[4];
#pragma unroll
    for (int g = 0; g < 4; g++) {
        int n = g * CC + ch;
        gate[g] = g_part[0][base + n] + g_part[1][base + n] + g_part[2][base + n]
                + b_ih[n] + b_hh[n];
    }
    float cc = g_c[i];
    cc = sigf(gate[1]) * cc + sigf(gate[0]) * tanhf(gate[2]);
    float h = sigf(gate[3]) * tanhf(cc);
    g_c[i] = cc;
    g_h[i] = h;
    out[(size_t)b * (2 * CC) + ch] = h;   // q half of q_star
}

// ============================================================
// Kernel 4: fused segment attention + pooling, online softmax.
// One CTA per segment, 256 threads, 32-row smem chunks.
// Single pass over x per step. Writes r-half of d_out.
// ============================================================
__global__ void attn_pool_kernel(const float* __restrict__ x,
                                 float* __restrict__ out) {
    const int b = blockIdx.x;
    const int tid = threadIdx.x;
    const int lane = tid & 31, w = tid >> 5;

    __shared__ float xs[32 * CC];   // 32 KB chunk
    __shared__ float ebuf[32];
    __shared__ float pbuf[32];

    // q for this segment: each lane holds q[lane + 32j] (per-warp full copy)
    const float* q = g_h + (size_t)b * CC;
    float qreg[8];
#pragma unroll
    for (int j = 0; j < 8; j++) qreg[j] = q[lane + 32 * j];

    float m = -INFINITY, ssum = 0.f, r = 0.f;
    const float* xb = x + (size_t)b * LL * CC;

    for (int ch = 0; ch < LL / 32; ch++) {
        // load chunk (32 rows x 256 cols) as float4
        const float4* src = (const float4*)(xb + (size_t)ch * 32 * CC);
        float4* dst = (float4*)xs;
#pragma unroll
        for (int i = tid; i < 32 * CC / 4; i += 256) dst[i] = src[i];
        __syncthreads();

        // row dots: warp w handles rows 4w..4w+3
#pragma unroll
        for (int jj = 0; jj < 4; jj++) {
            int l = w * 4 + jj;
            const float* row = xs + l * CC;
            float d = 0.f;
#pragma unroll
            for (int j = 0; j < 8; j++) d = fmaf(row[lane + 32 * j], qreg[j], d);
#pragma unroll
            for (int off = 16; off; off >>= 1) d += __shfl_xor_sync(0xffffffffu, d, off);
            if (lane == 0) ebuf[l] = d;
        }
        __syncthreads();

        float cm = ebuf[0];
#pragma unroll
        for (int l = 1; l < 32; l++) cm = fmaxf(cm, ebuf[l]);
        float newm = fmaxf(m, cm);
        if (tid < 32) pbuf[tid] = expf(ebuf[tid] - newm);
        float alpha = expf(m - newm);   // first chunk: exp(-inf)=0, r==0 anyway
        __syncthreads();

        r *= alpha; ssum *= alpha;
        float ps = 0.f;
#pragma unroll
        for (int l = 0; l < 32; l++) {
            float p = pbuf[l];
            r = fmaf(p, xs[l * CC + tid], r);
            ps += p;
        }
        ssum += ps;
        m = newm;
        __syncthreads();   // protect xs/ebuf/pbuf before next chunk
    }

    out[(size_t)b * (2 * CC) + CC + tid] = r / (ssum + 1e-16f);
}

// ============================================================
// launch
// ============================================================
extern "C" void kernel_launch(void* const* d_in, const int* in_sizes, int n_in,
                              void* d_out, int out_size) {
    const float* x      = (const float*)d_in[0];
    // d_in[1] = batch (unused: segments are contiguous, L=256 each)
    const float* q_star = (const float*)d_in[2];
    const float* bank_s = (const float*)d_in[3];
    const float* w_ih   = (const float*)d_in[4];
    const float* w_hh   = (const float*)d_in[5];
    const float* b_ih   = (const float*)d_in[6];
    const float* b_hh   = (const float*)d_in[7];
    const int*   index  = (const int*)d_in[8];
    float* out = (float*)d_out;

    asit_kernel<<<BB, 256>>>(x, bank_s, index);

    for (int t = 0; t < 3; t++) {
        const float* qs = (t == 0) ? q_star : out;   // q_star lives in d_out after step 0
        dim3 ggrid(16, 8, 3);
        gemm_slice_kernel<<<ggrid, 256>>>(qs, w_ih, w_hh);
        lstm_elem_kernel<<<BB, 256>>>(b_ih, b_hh, out);
        attn_pool_kernel<<<BB, 256>>>(x, out);
    }
}

// round 4
// speedup vs baseline: 1.4994x; 1.4994x over previous
#include <cuda_runtime.h>
#include <cuda_bf16.h>
#include <math.h>
#include <stdint.h>

#define CC 256     // channels
#define BB 512     // segments
#define LL 256     // nodes per segment
#define RR 8       // bank rows
#define KK 768     // GEMM K  (512 q_star + 256 h)
#define NG 1024    // 4*C gate outputs

// ------------------- scratch (device globals) -------------------
__device__ __align__(128) __nv_bfloat16 g_A_hi[BB * KK];
__device__ __align__(128) __nv_bfloat16 g_A_lo[BB * KK];
__device__ __align__(128) __nv_bfloat16 g_W_hi[NG * KK];
__device__ __align__(128) __nv_bfloat16 g_W_lo[NG * KK];
__device__ __align__(128) float g_gates[BB * NG];
__device__ __align__(128) float g_h[BB * CC];
__device__ __align__(128) float g_c[BB * CC];

// ------------------- helpers -------------------
__device__ __forceinline__ uint32_t smem_u32(const void* p) {
    uint32_t a;
    asm("{ .reg .u64 t; cvta.to.shared.u64 t, %1; cvt.u32.u64 %0, t; }" : "=r"(a) : "l"(p));
    return a;
}

#define CP16(dst, src) \
    asm volatile("cp.async.cg.shared.global [%0], [%1], 16;\n" :: "r"(dst), "l"(src))
#define CP_COMMIT() asm volatile("cp.async.commit_group;\n" ::: "memory")
#define CP_WAIT1()  asm volatile("cp.async.wait_group 1;\n" ::: "memory")
#define CP_WAIT0()  asm volatile("cp.async.wait_group 0;\n" ::: "memory")

__device__ __forceinline__ void ldsm4(uint32_t* r, uint32_t addr) {
    asm volatile("ldmatrix.sync.aligned.m8n8.x4.shared.b16 {%0,%1,%2,%3}, [%4];"
                 : "=r"(r[0]), "=r"(r[1]), "=r"(r[2]), "=r"(r[3]) : "r"(addr));
}

__device__ __forceinline__ void mma16816(float* c, const uint32_t* a, const uint32_t* b) {
    asm volatile(
        "mma.sync.aligned.m16n8k16.row.col.f32.bf16.bf16.f32 "
        "{%0,%1,%2,%3}, {%4,%5,%6,%7}, {%8,%9}, {%0,%1,%2,%3};"
        : "+f"(c[0]), "+f"(c[1]), "+f"(c[2]), "+f"(c[3])
        : "r"(a[0]), "r"(a[1]), "r"(a[2]), "r"(a[3]), "r"(b[0]), "r"(b[1]));
}

__device__ __forceinline__ void split_bf16(float v, __nv_bfloat16& hi, __nv_bfloat16& lo) {
    hi = __float2bfloat16(v);
    lo = __float2bfloat16(v - __bfloat162float(hi));
}
__device__ __forceinline__ float sigf(float v) { return 1.f / (1.f + expf(-v)); }

// ============================================================
// W conversion: W = [w_ih | w_hh] per row, split hi/lo bf16
// ============================================================
__global__ void wconv_kernel(const float* __restrict__ w_ih,
                             const float* __restrict__ w_hh) {
    int i = blockIdx.x * 256 + threadIdx.x;    // 0 .. NG*KK-1
    int n = i / KK, c = i - n * KK;
    float v = (c < 2 * CC) ? w_ih[n * (2 * CC) + c] : w_hh[n * CC + (c - 2 * CC)];
    __nv_bfloat16 hi, lo;
    split_bf16(v, hi, lo);
    g_W_hi[i] = hi;
    g_W_lo[i] = lo;
}

// q_star input -> A cols [0,512)
__global__ void qconv_kernel(const float* __restrict__ q_star) {
    int i = blockIdx.x * 256 + threadIdx.x;    // 0 .. BB*512-1
    int r = i >> 9, c = i & 511;
    __nv_bfloat16 hi, lo;
    split_bf16(q_star[i], hi, lo);
    g_A_hi[r * KK + c] = hi;
    g_A_lo[r * KK + c] = lo;
}

// ============================================================
// a_sit + init: h = bank_s[b,index] @ x_seg ; c = 0 ; A cols [512,768)
// ============================================================
__global__ void asit_kernel(const float* __restrict__ x,
                            const float* __restrict__ bank_s,
                            const int* __restrict__ index_p) {
    int b = blockIdx.x;
    int c = threadIdx.x;
    __shared__ float s[LL];
    int idx = *index_p;
    s[c] = bank_s[((size_t)b * RR + idx) * LL + c];
    __syncthreads();
    const float* xb = x + (size_t)b * LL * CC;
    float acc = 0.f;
#pragma unroll 16
    for (int l = 0; l < LL; l++)
        acc = fmaf(s[l], xb[(size_t)l * CC + c], acc);
    g_h[b * CC + c] = acc;
    g_c[b * CC + c] = 0.f;
    __nv_bfloat16 hi, lo;
    split_bf16(acc, hi, lo);
    g_A_hi[b * KK + 512 + c] = hi;
    g_A_lo[b * KK + 512 + c] = lo;
}

// ============================================================
// bf16x3 tensor-core GEMM via mma.sync (sm_80+ path; no tcgen05):
// gates[512,1024] = A[512,768] @ W[1024,768]^T
// CTA tile 64x64, 4 warps (warp tile 32x32), K-chunk 32, double buffered.
// smem rows padded to 112B (conflict-free, 16B-aligned ldmatrix).
// grid (16, 8) = 128 CTAs.
// ============================================================
#define RSTRIDE 112                   // bytes per 32-elem bf16 row (padded)
#define MAT_BYTES (64 * RSTRIDE)      // 7168 per matrix
#define BUF_BYTES (4 * MAT_BYTES)     // Ah, Al, Wh, Wl
#define GEMM_SMEM (2 * BUF_BYTES)     // 57344

__global__ __launch_bounds__(128, 1)
void gemm_kernel() {
    extern __shared__ char smem[];
    const uint32_t sb = smem_u32(smem);
    const int tid = threadIdx.x;
    const int lane = tid & 31, wid = tid >> 5;
    const int wm = wid >> 1, wn = wid & 1;        // 2x2 warp grid
    const int m0 = blockIdx.y * 64;
    const int n0 = blockIdx.x * 64;

    float acc[2][4][4];
#pragma unroll
    for (int i = 0; i < 2; i++)
#pragma unroll
        for (int j = 0; j < 4; j++)
#pragma unroll
            for (int k = 0; k < 4; k++) acc[i][j][k] = 0.f;

    // per-chunk async copy: 4 matrices x 64 rows x 2 units(16B) ... = 1024 units/128 thr
    auto cp_chunk = [&](int c) {
        const int k0 = c * 32;
        const uint32_t bo = sb + (c & 1) * BUF_BYTES;
        const __nv_bfloat16* srcs[4] = {
            g_A_hi + (size_t)m0 * KK + k0, g_A_lo + (size_t)m0 * KK + k0,
            g_W_hi + (size_t)n0 * KK + k0, g_W_lo + (size_t)n0 * KK + k0 };
#pragma unroll
        for (int i = 0; i < 8; i++) {
            int u = tid + i * 128;            // 0..1023
            int mat = u >> 8;                 // 0..3
            int w = u & 255;
            int row = w >> 2, cu = w & 3;     // 4 x 16B per row
            uint32_t dst = bo + mat * MAT_BYTES + row * RSTRIDE + cu * 16;
            const __nv_bfloat16* src = srcs[mat] + (size_t)row * KK + cu * 8;
            CP16(dst, src);
        }
    };

    cp_chunk(0);
    CP_COMMIT();

    // ldmatrix lane addressing offsets
    const int a_row = (lane & 15);                 // within m16 tile
    const int a_kb  = (lane >> 4) * 16;            // 0 / 16 bytes
    const int b_row = (lane & 7) + ((lane >> 4) << 3);   // within n16 pair
    const int b_kb  = ((lane >> 3) & 1) * 16;

    for (int c = 0; c < 24; c++) {
        if (c + 1 < 24) {
            cp_chunk(c + 1);
            CP_COMMIT();
            CP_WAIT1();
        } else {
            CP_WAIT0();
        }
        __syncthreads();

        const uint32_t bo = sb + (c & 1) * BUF_BYTES;
#pragma unroll
        for (int s = 0; s < 2; s++) {               // two k16 steps
            const int kb = s * 32;
            uint32_t ah[2][4], al[2][4], bh[2][4], bl[2][4];
#pragma unroll
            for (int mt = 0; mt < 2; mt++) {
                uint32_t ra = (wm * 32 + mt * 16 + a_row) * RSTRIDE + kb + a_kb;
                ldsm4(ah[mt], bo + 0 * MAT_BYTES + ra);
                ldsm4(al[mt], bo + 1 * MAT_BYTES + ra);
            }
#pragma unroll
            for (int np = 0; np < 2; np++) {
                uint32_t rb = (wn * 32 + np * 16 + b_row) * RSTRIDE + kb + b_kb;
                ldsm4(bh[np], bo + 2 * MAT_BYTES + rb);
                ldsm4(bl[np], bo + 3 * MAT_BYTES + rb);
            }
            // term 1: Ah*Wh
#pragma unroll
            for (int mt = 0; mt < 2; mt++)
#pragma unroll
                for (int nf = 0; nf < 4; nf++)
                    mma16816(acc[mt][nf], ah[mt], &bh[nf >> 1][(nf & 1) * 2]);
            // term 2: Ah*Wl
#pragma unroll
            for (int mt = 0; mt < 2; mt++)
#pragma unroll
                for (int nf = 0; nf < 4; nf++)
                    mma16816(acc[mt][nf], ah[mt], &bl[nf >> 1][(nf & 1) * 2]);
            // term 3: Al*Wh
#pragma unroll
            for (int mt = 0; mt < 2; mt++)
#pragma unroll
                for (int nf = 0; nf < 4; nf++)
                    mma16816(acc[mt][nf], al[mt], &bh[nf >> 1][(nf & 1) * 2]);
        }
        __syncthreads();   // protect smem buffer reuse (WAR vs next cp_chunk)
    }

    // epilogue: d0={r,c}, d1={r,c+1}, d2={r+8,c}, d3={r+8,c+1}; r=lane/4, c=(lane%4)*2
    const int er = lane >> 2, ec = (lane & 3) * 2;
#pragma unroll
    for (int mt = 0; mt < 2; mt++) {
        int row = m0 + wm * 32 + mt * 16 + er;
#pragma unroll
        for (int nf = 0; nf < 4; nf++) {
            int col = n0 + wn * 32 + nf * 8 + ec;
            *(float2*)&g_gates[(size_t)row * NG + col] =
                make_float2(acc[mt][nf][0], acc[mt][nf][1]);
            *(float2*)&g_gates[(size_t)(row + 8) * NG + col] =
                make_float2(acc[mt][nf][2], acc[mt][nf][3]);
        }
    }
}

// ============================================================
// LSTM elementwise; writes h (f32 + A hi/lo cols 0-255 & 512-767) + q-half out
// ============================================================
__global__ void lstm_kernel(const float* __restrict__ b_ih,
                            const float* __restrict__ b_hh,
                            float* __restrict__ out) {
    int i = blockIdx.x * 256 + threadIdx.x;   // 0 .. BB*CC-1
    int b = i >> 8, ch = i & 255;
    const float* gr = g_gates + (size_t)b * NG;
    float ig = gr[ch]        + b_ih[ch]        + b_hh[ch];
    float fg = gr[256 + ch]  + b_ih[256 + ch]  + b_hh[256 + ch];
    float gg = gr[512 + ch]  + b_ih[512 + ch]  + b_hh[512 + ch];
    float og = gr[768 + ch]  + b_ih[768 + ch]  + b_hh[768 + ch];
    float cc = sigf(fg) * g_c[i] + sigf(ig) * tanhf(gg);
    float h  = sigf(og) * tanhf(cc);
    g_c[i] = cc;
    g_h[i] = h;
    out[(size_t)b * (2 * CC) + ch] = h;
    __nv_bfloat16 hi, lo;
    split_bf16(h, hi, lo);
    g_A_hi[b * KK + ch] = hi;        g_A_lo[b * KK + ch] = lo;
    g_A_hi[b * KK + 512 + ch] = hi;  g_A_lo[b * KK + 512 + ch] = lo;
}

// ============================================================
// Fused segment attention + pooling, online softmax,
// cp.async double-buffered 16-row chunks (32 KB smem).
// Writes r-half of out + A cols [256,512) hi/lo.
// ============================================================
__global__ void attn_kernel(const float* __restrict__ x, float* __restrict__ out) {
    extern __shared__ float xs[];            // 2 * 16*256 floats = 32 KB
    __shared__ float ebuf[16], pbuf[16];
    const int b = blockIdx.x, tid = threadIdx.x;
    const int lane = tid & 31, w = tid >> 5;

    const float* q = g_h + (size_t)b * CC;
    float qreg[8];
#pragma unroll
    for (int j = 0; j < 8; j++) qreg[j] = q[lane + 32 * j];

    float m = -INFINITY, ssum = 0.f, r = 0.f;
    const float* xb = x + (size_t)b * LL * CC;
    uint32_t sbx = smem_u32(xs);

    auto cp_chunk = [&](int ch) {
        const float* src = xb + (size_t)ch * 16 * CC;
        uint32_t dst = sbx + (ch & 1) * 16384;
#pragma unroll
        for (int i = 0; i < 4; i++)
            CP16(dst + (tid + i * 256) * 16, src + (tid + i * 256) * 4);
    };

    cp_chunk(0);
    CP_COMMIT();

    for (int ch = 0; ch < 16; ch++) {
        if (ch + 1 < 16) {
            cp_chunk(ch + 1);
            CP_COMMIT();
            CP_WAIT1();
        } else {
            CP_WAIT0();
        }
        __syncthreads();
        const float* cx = xs + (ch & 1) * 4096;

        // dot products: warp w handles rows 2w, 2w+1
#pragma unroll
        for (int jj = 0; jj < 2; jj++) {
            int l = w * 2 + jj;
            const float* row = cx + l * CC;
            float d = 0.f;
#pragma unroll
            for (int j = 0; j < 8; j++) d = fmaf(row[lane + 32 * j], qreg[j], d);
#pragma unroll
            for (int off = 16; off; off >>= 1) d += __shfl_xor_sync(0xffffffffu, d, off);
            if (lane == 0) ebuf[l] = d;
        }
        __syncthreads();

        float cm = ebuf[0];
#pragma unroll
        for (int l = 1; l < 16; l++) cm = fmaxf(cm, ebuf[l]);
        float nm = fmaxf(m, cm);
        if (tid < 16) pbuf[tid] = expf(ebuf[tid] - nm);
        float alpha = expf(m - nm);   // first chunk: exp(-inf) = 0
        __syncthreads();

        r *= alpha; ssum *= alpha;
        float ps = 0.f;
#pragma unroll
        for (int l = 0; l < 16; l++) {
            float p = pbuf[l];
            r = fmaf(p, cx[l * CC + tid], r);
            ps += p;
        }
        ssum += ps;
        m = nm;
        __syncthreads();
    }

    float rr = r / (ssum + 1e-16f);
    out[(size_t)b * (2 * CC) + CC + tid] = rr;
    __nv_bfloat16 hi, lo;
    split_bf16(rr, hi, lo);
    g_A_hi[b * KK + 256 + tid] = hi;
    g_A_lo[b * KK + 256 + tid] = lo;
}

// ============================================================
// launch
// ============================================================
extern "C" void kernel_launch(void* const* d_in, const int* in_sizes, int n_in,
                              void* d_out, int out_size) {
    const float* x      = (const float*)d_in[0];
    // d_in[1] = batch (unused: segments contiguous, L=256 each)
    const float* q_star = (const float*)d_in[2];
    const float* bank_s = (const float*)d_in[3];
    const float* w_ih   = (const float*)d_in[4];
    const float* w_hh   = (const float*)d_in[5];
    const float* b_ih   = (const float*)d_in[6];
    const float* b_hh   = (const float*)d_in[7];
    const int*   index  = (const int*)d_in[8];
    float* out = (float*)d_out;

    cudaFuncSetAttribute(gemm_kernel, cudaFuncAttributeMaxDynamicSharedMemorySize, GEMM_SMEM);

    wconv_kernel<<<(NG * KK) / 256, 256>>>(w_ih, w_hh);
    qconv_kernel<<<(BB * 512) / 256, 256>>>(q_star);
    asit_kernel<<<BB, 256>>>(x, bank_s, index);

    for (int t = 0; t < 3; t++) {
        gemm_kernel<<<dim3(16, 8), 128, GEMM_SMEM>>>();
        lstm_kernel<<<BB, 256>>>(b_ih, b_hh, out);
        attn_kernel<<<BB, 256, 32768>>>(x, out);
    }
}

// round 10
// speedup vs baseline: 1.5550x; 1.0370x over previous
#include <cuda_runtime.h>
#include <cuda_bf16.h>
#include <math.h>
#include <stdint.h>

#define CC 256     // channels
#define BB 512     // segments
#define LL 256     // nodes per segment
#define RR 8       // bank rows
#define K0 768     // step-0 GEMM K  (512 q_star + 256 h)
#define K1 512     // step-1/2 GEMM K (256 h + 256 r), combined weights
#define NG 1024    // 4*C gate outputs

// ------------------- scratch (device globals) -------------------
// NEVER referenced from host code (host shadow address != device address;
// doing so silently grows a 128MiB HMM pool and trips the alloc guard).
__device__ __align__(128) __nv_bfloat16 g_A_hi[BB * K0];
__device__ __align__(128) __nv_bfloat16 g_A_lo[BB * K0];
__device__ __align__(128) __nv_bfloat16 g_A2_hi[BB * K1];
__device__ __align__(128) __nv_bfloat16 g_A2_lo[BB * K1];
__device__ __align__(128) __nv_bfloat16 g_W_hi[NG * K0];
__device__ __align__(128) __nv_bfloat16 g_W_lo[NG * K0];
__device__ __align__(128) __nv_bfloat16 g_W2_hi[NG * K1];
__device__ __align__(128) __nv_bfloat16 g_W2_lo[NG * K1];
__device__ __align__(128) float g_gates[BB * NG];
__device__ __align__(128) float g_h[BB * CC];
__device__ __align__(128) float g_c[BB * CC];

// ------------------- helpers -------------------
__device__ __forceinline__ uint32_t smem_u32(const void* p) {
    uint32_t a;
    asm("{ .reg .u64 t; cvta.to.shared.u64 t, %1; cvt.u32.u64 %0, t; }" : "=r"(a) : "l"(p));
    return a;
}

#define CP16(dst, src) \
    asm volatile("cp.async.cg.shared.global [%0], [%1], 16;\n" :: "r"(dst), "l"(src))
#define CP_COMMIT() asm volatile("cp.async.commit_group;\n" ::: "memory")
#define CP_WAIT1()  asm volatile("cp.async.wait_group 1;\n" ::: "memory")
#define CP_WAIT0()  asm volatile("cp.async.wait_group 0;\n" ::: "memory")

__device__ __forceinline__ void ldsm4(uint32_t* r, uint32_t addr) {
    asm volatile("ldmatrix.sync.aligned.m8n8.x4.shared.b16 {%0,%1,%2,%3}, [%4];"
                 : "=r"(r[0]), "=r"(r[1]), "=r"(r[2]), "=r"(r[3]) : "r"(addr));
}

__device__ __forceinline__ void mma16816(float* c, const uint32_t* a, const uint32_t* b) {
    asm volatile(
        "mma.sync.aligned.m16n8k16.row.col.f32.bf16.bf16.f32 "
        "{%0,%1,%2,%3}, {%4,%5,%6,%7}, {%8,%9}, {%0,%1,%2,%3};"
        : "+f"(c[0]), "+f"(c[1]), "+f"(c[2]), "+f"(c[3])
        : "r"(a[0]), "r"(a[1]), "r"(a[2]), "r"(a[3]), "r"(b[0]), "r"(b[1]));
}

__device__ __forceinline__ void split_bf16(float v, __nv_bfloat16& hi, __nv_bfloat16& lo) {
    hi = __float2bfloat16(v);
    lo = __float2bfloat16(v - __bfloat162float(hi));
}
__device__ __forceinline__ float sigf(float v) { return 1.f / (1.f + expf(-v)); }

// ============================================================
// W conversions
// ============================================================
__global__ void wconv_kernel(const float* __restrict__ w_ih,
                             const float* __restrict__ w_hh) {
    int i = blockIdx.x * 256 + threadIdx.x;    // 0 .. NG*K0-1
    int n = i / K0, c = i - n * K0;
    float v = (c < 2 * CC) ? w_ih[n * (2 * CC) + c] : w_hh[n * CC + (c - 2 * CC)];
    __nv_bfloat16 hi, lo;
    split_bf16(v, hi, lo);
    g_W_hi[i] = hi;
    g_W_lo[i] = lo;
}

// step-1/2 weights: [w_ih[:, :256] + w_hh  |  w_ih[:, 256:512]], K=512
// (valid because q_star = [h | r] for t >= 1)
__global__ void wconv2_kernel(const float* __restrict__ w_ih,
                              const float* __restrict__ w_hh) {
    int i = blockIdx.x * 256 + threadIdx.x;    // 0 .. NG*K1-1
    int n = i >> 9, c = i & 511;
    float v = (c < CC) ? (w_ih[n * (2 * CC) + c] + w_hh[n * CC + c])
                       : w_ih[n * (2 * CC) + c];
    __nv_bfloat16 hi, lo;
    split_bf16(v, hi, lo);
    g_W2_hi[i] = hi;
    g_W2_lo[i] = lo;
}

// q_star input -> A cols [0,512)  (step 0 only)
__global__ void qconv_kernel(const float* __restrict__ q_star) {
    int i = blockIdx.x * 256 + threadIdx.x;    // 0 .. BB*512-1
    int r = i >> 9, c = i & 511;
    __nv_bfloat16 hi, lo;
    split_bf16(q_star[i], hi, lo);
    g_A_hi[r * K0 + c] = hi;
    g_A_lo[r * K0 + c] = lo;
}

// ============================================================
// a_sit + init: h = bank_s[b,index] @ x_seg ; c = 0 ; A cols [512,768)
// ============================================================
__global__ void asit_kernel(const float* __restrict__ x,
                            const float* __restrict__ bank_s,
                            const int* __restrict__ index_p) {
    int b = blockIdx.x;
    int c = threadIdx.x;
    __shared__ float s[LL];
    int idx = *index_p;
    s[c] = bank_s[((size_t)b * RR + idx) * LL + c];
    __syncthreads();
    const float* xb = x + (size_t)b * LL * CC;
    float acc = 0.f;
#pragma unroll 16
    for (int l = 0; l < LL; l++)
        acc = fmaf(s[l], xb[(size_t)l * CC + c], acc);
    g_h[b * CC + c] = acc;
    g_c[b * CC + c] = 0.f;
    __nv_bfloat16 hi, lo;
    split_bf16(acc, hi, lo);
    g_A_hi[b * K0 + 512 + c] = hi;
    g_A_lo[b * K0 + 512 + c] = lo;
}

// ============================================================
// bf16x3 tensor-core GEMM (round-4 body, 0 lmem), templated on K;
// buffers selected in device code (compile-time).
// CTA tile 64x64, 4 warps, K-chunk 32, double buffered, 128 threads.
// ============================================================
#define RSTRIDE 112
#define MAT_BYTES (64 * RSTRIDE)
#define BUF_BYTES (4 * MAT_BYTES)
#define GEMM_SMEM (2 * BUF_BYTES)     // 57344

template <int K>
__global__ __launch_bounds__(128, 1)
void gemm_kernel() {
    constexpr int NC = K / 32;
    const __nv_bfloat16* __restrict__ Ah = (K == K0) ? g_A_hi : g_A2_hi;
    const __nv_bfloat16* __restrict__ Al = (K == K0) ? g_A_lo : g_A2_lo;
    const __nv_bfloat16* __restrict__ Wh = (K == K0) ? g_W_hi : g_W2_hi;
    const __nv_bfloat16* __restrict__ Wl = (K == K0) ? g_W_lo : g_W2_lo;

    extern __shared__ char smem[];
    const uint32_t sb = smem_u32(smem);
    const int tid = threadIdx.x;
    const int lane = tid & 31, wid = tid >> 5;
    const int wm = wid >> 1, wn = wid & 1;
    const int m0 = blockIdx.y * 64;
    const int n0 = blockIdx.x * 64;

    float acc[2][4][4];
#pragma unroll
    for (int i = 0; i < 2; i++)
#pragma unroll
        for (int j = 0; j < 4; j++)
#pragma unroll
            for (int k = 0; k < 4; k++) acc[i][j][k] = 0.f;

    auto cp_chunk = [&](int c) {
        const int k0 = c * 32;
        const uint32_t bo = sb + (c & 1) * BUF_BYTES;
#pragma unroll
        for (int rep = 0; rep < 2; rep++) {
            int u = tid + rep * 128;
            int row = u >> 2, cu = u & 3;
            uint32_t doff = bo + row * RSTRIDE + cu * 16;
            size_t aoff = (size_t)(m0 + row) * K + k0 + cu * 8;
            size_t woff = (size_t)(n0 + row) * K + k0 + cu * 8;
            CP16(doff + 0 * MAT_BYTES, Ah + aoff);
            CP16(doff + 1 * MAT_BYTES, Al + aoff);
            CP16(doff + 2 * MAT_BYTES, Wh + woff);
            CP16(doff + 3 * MAT_BYTES, Wl + woff);
        }
    };

    cp_chunk(0);
    CP_COMMIT();

    const int a_row = (lane & 15);
    const int a_kb  = (lane >> 4) * 16;
    const int b_row = (lane & 7) + ((lane >> 4) << 3);
    const int b_kb  = ((lane >> 3) & 1) * 16;

    for (int c = 0; c < NC; c++) {
        if (c + 1 < NC) {
            cp_chunk(c + 1);
            CP_COMMIT();
            CP_WAIT1();
        } else {
            CP_WAIT0();
        }
        __syncthreads();

        const uint32_t bo = sb + (c & 1) * BUF_BYTES;
#pragma unroll
        for (int s = 0; s < 2; s++) {
            const int kb = s * 32;
            uint32_t ah[2][4], al[2][4], bh[2][4], bl[2][4];
#pragma unroll
            for (int mt = 0; mt < 2; mt++) {
                uint32_t ra = (wm * 32 + mt * 16 + a_row) * RSTRIDE + kb + a_kb;
                ldsm4(ah[mt], bo + 0 * MAT_BYTES + ra);
                ldsm4(al[mt], bo + 1 * MAT_BYTES + ra);
            }
#pragma unroll
            for (int np = 0; np < 2; np++) {
                uint32_t rb = (wn * 32 + np * 16 + b_row) * RSTRIDE + kb + b_kb;
                ldsm4(bh[np], bo + 2 * MAT_BYTES + rb);
                ldsm4(bl[np], bo + 3 * MAT_BYTES + rb);
            }
#pragma unroll
            for (int mt = 0; mt < 2; mt++)
#pragma unroll
                for (int nf = 0; nf < 4; nf++)
                    mma16816(acc[mt][nf], ah[mt], &bh[nf >> 1][(nf & 1) * 2]);
#pragma unroll
            for (int mt = 0; mt < 2; mt++)
#pragma unroll
                for (int nf = 0; nf < 4; nf++)
                    mma16816(acc[mt][nf], ah[mt], &bl[nf >> 1][(nf & 1) * 2]);
#pragma unroll
            for (int mt = 0; mt < 2; mt++)
#pragma unroll
                for (int nf = 0; nf < 4; nf++)
                    mma16816(acc[mt][nf], al[mt], &bh[nf >> 1][(nf & 1) * 2]);
        }
        __syncthreads();
    }

    const int er = lane >> 2, ec = (lane & 3) * 2;
#pragma unroll
    for (int mt = 0; mt < 2; mt++) {
        int row = m0 + wm * 32 + mt * 16 + er;
#pragma unroll
        for (int nf = 0; nf < 4; nf++) {
            int col = n0 + wn * 32 + nf * 8 + ec;
            *(float2*)&g_gates[(size_t)row * NG + col] =
                make_float2(acc[mt][nf][0], acc[mt][nf][1]);
            *(float2*)&g_gates[(size_t)(row + 8) * NG + col] =
                make_float2(acc[mt][nf][2], acc[mt][nf][3]);
        }
    }
}

// ============================================================
// LSTM elementwise; writes h -> g_h, q-half of out, A2 cols [0,256)
// ============================================================
__global__ void lstm_kernel(const float* __restrict__ b_ih,
                            const float* __restrict__ b_hh,
                            float* __restrict__ out) {
    int i = blockIdx.x * 256 + threadIdx.x;
    int b = i >> 8, ch = i & 255;
    const float* gr = g_gates + (size_t)b * NG;
    float ig = gr[ch]        + b_ih[ch]        + b_hh[ch];
    float fg = gr[256 + ch]  + b_ih[256 + ch]  + b_hh[256 + ch];
    float gg = gr[512 + ch]  + b_ih[512 + ch]  + b_hh[512 + ch];
    float og = gr[768 + ch]  + b_ih[768 + ch]  + b_hh[768 + ch];
    float cc = sigf(fg) * g_c[i] + sigf(ig) * tanhf(gg);
    float h  = sigf(og) * tanhf(cc);
    g_c[i] = cc;
    g_h[i] = h;
    out[(size_t)b * (2 * CC) + ch] = h;
    __nv_bfloat16 hi, lo;
    split_bf16(h, hi, lo);
    g_A2_hi[b * K1 + ch] = hi;
    g_A2_lo[b * K1 + ch] = lo;
}

// ============================================================
// Fused segment attention + pooling, online softmax,
// cp.async double-buffered 16-row chunks. Writes r-half + A2 [256,512).
// ============================================================
__global__ void attn_kernel(const float* __restrict__ x, float* __restrict__ out) {
    extern __shared__ float xs[];            // 32 KB
    __shared__ float ebuf[16], pbuf[16];
    const int b = blockIdx.x, tid = threadIdx.x;
    const int lane = tid & 31, w = tid >> 5;

    const float* q = g_h + (size_t)b * CC;
    float qreg[8];
#pragma unroll
    for (int j = 0; j < 8; j++) qreg[j] = q[lane + 32 * j];

    float m = -INFINITY, ssum = 0.f, r = 0.f;
    const float* xb = x + (size_t)b * LL * CC;
    uint32_t sbx = smem_u32(xs);

    auto cp_chunk = [&](int ch) {
        const float* src = xb + (size_t)ch * 16 * CC;
        uint32_t dst = sbx + (ch & 1) * 16384;
#pragma unroll
        for (int i = 0; i < 4; i++)
            CP16(dst + (tid + i * 256) * 16, src + (tid + i * 256) * 4);
    };

    cp_chunk(0);
    CP_COMMIT();

    for (int ch = 0; ch < 16; ch++) {
        if (ch + 1 < 16) {
            cp_chunk(ch + 1);
            CP_COMMIT();
            CP_WAIT1();
        } else {
            CP_WAIT0();
        }
        __syncthreads();
        const float* cx = xs + (ch & 1) * 4096;

#pragma unroll
        for (int jj = 0; jj < 2; jj++) {
            int l = w * 2 + jj;
            const float* row = cx + l * CC;
            float d = 0.f;
#pragma unroll
            for (int j = 0; j < 8; j++) d = fmaf(row[lane + 32 * j], qreg[j], d);
#pragma unroll
            for (int off = 16; off; off >>= 1) d += __shfl_xor_sync(0xffffffffu, d, off);
            if (lane == 0) ebuf[l] = d;
        }
        __syncthreads();

        float cm = ebuf[0];
#pragma unroll
        for (int l = 1; l < 16; l++) cm = fmaxf(cm, ebuf[l]);
        float nm = fmaxf(m, cm);
        if (tid < 16) pbuf[tid] = expf(ebuf[tid] - nm);
        float alpha = expf(m - nm);
        __syncthreads();

        r *= alpha; ssum *= alpha;
        float ps = 0.f;
#pragma unroll
        for (int l = 0; l < 16; l++) {
            float p = pbuf[l];
            r = fmaf(p, cx[l * CC + tid], r);
            ps += p;
        }
        ssum += ps;
        m = nm;
        __syncthreads();
    }

    float rr = r / (ssum + 1e-16f);
    out[(size_t)b * (2 * CC) + CC + tid] = rr;
    __nv_bfloat16 hi, lo;
    split_bf16(rr, hi, lo);
    g_A2_hi[b * K1 + 256 + tid] = hi;
    g_A2_lo[b * K1 + 256 + tid] = lo;
}

// ============================================================
// launch
// ============================================================
extern "C" void kernel_launch(void* const* d_in, const int* in_sizes, int n_in,
                              void* d_out, int out_size) {
    const float* x      = (const float*)d_in[0];
    const float* q_star = (const float*)d_in[2];
    const float* bank_s = (const float*)d_in[3];
    const float* w_ih   = (const float*)d_in[4];
    const float* w_hh   = (const float*)d_in[5];
    const float* b_ih   = (const float*)d_in[6];
    const float* b_hh   = (const float*)d_in[7];
    const int*   index  = (const int*)d_in[8];
    float* out = (float*)d_out;

    cudaFuncSetAttribute(gemm_kernel<K0>, cudaFuncAttributeMaxDynamicSharedMemorySize, GEMM_SMEM);
    cudaFuncSetAttribute(gemm_kernel<K1>, cudaFuncAttributeMaxDynamicSharedMemorySize, GEMM_SMEM);

    wconv_kernel<<<(NG * K0) / 256, 256>>>(w_ih, w_hh);
    wconv2_kernel<<<(NG * K1) / 256, 256>>>(w_ih, w_hh);
    qconv_kernel<<<(BB * 512) / 256, 256>>>(q_star);
    asit_kernel<<<BB, 256>>>(x, bank_s, index);

    for (int t = 0; t < 3; t++) {
        if (t == 0)
            gemm_kernel<K0><<<dim3(16, 8), 128, GEMM_SMEM>>>();
        else
            gemm_kernel<K1><<<dim3(16, 8), 128, GEMM_SMEM>>>();
        lstm_kernel<<<BB, 256>>>(b_ih, b_hh, out);
        attn_kernel<<<BB, 256, 32768>>>(x, out);
    }
}

// round 11
// speedup vs baseline: 1.6391x; 1.0541x over previous
#include <cuda_runtime.h>
#include <cuda_bf16.h>
#include <math.h>
#include <stdint.h>

#define CC 256     // channels
#define BB 512     // segments
#define LL 256     // nodes per segment
#define RR 8       // bank rows
#define K0 768     // step-0 GEMM K  (512 q_star + 256 h)
#define K1 512     // step-1/2 GEMM K (256 h + 256 r), combined weights
#define NG 1024    // 4*C gate outputs

// ------------------- scratch (device globals) -------------------
// NEVER referenced from host code (host shadow address != device address;
// doing so silently grows a 128MiB HMM pool and trips the alloc guard).
__device__ __align__(128) __nv_bfloat16 g_A_hi[BB * K0];
__device__ __align__(128) __nv_bfloat16 g_A_lo[BB * K0];
__device__ __align__(128) __nv_bfloat16 g_A2_hi[BB * K1];
__device__ __align__(128) __nv_bfloat16 g_A2_lo[BB * K1];
__device__ __align__(128) __nv_bfloat16 g_W_hi[NG * K0];
__device__ __align__(128) __nv_bfloat16 g_W_lo[NG * K0];
__device__ __align__(128) __nv_bfloat16 g_W2_hi[NG * K1];
__device__ __align__(128) __nv_bfloat16 g_W2_lo[NG * K1];
__device__ __align__(128) float g_gates[BB * NG];
__device__ __align__(128) float g_h[BB * CC];
__device__ __align__(128) float g_c[BB * CC];

// ------------------- helpers -------------------
__device__ __forceinline__ uint32_t smem_u32(const void* p) {
    uint32_t a;
    asm("{ .reg .u64 t; cvta.to.shared.u64 t, %1; cvt.u32.u64 %0, t; }" : "=r"(a) : "l"(p));
    return a;
}

#define CP16(dst, src) \
    asm volatile("cp.async.cg.shared.global [%0], [%1], 16;\n" :: "r"(dst), "l"(src))
#define CP_COMMIT() asm volatile("cp.async.commit_group;\n" ::: "memory")
#define CP_WAIT1()  asm volatile("cp.async.wait_group 1;\n" ::: "memory")
#define CP_WAIT0()  asm volatile("cp.async.wait_group 0;\n" ::: "memory")

__device__ __forceinline__ void ldsm4(uint32_t* r, uint32_t addr) {
    asm volatile("ldmatrix.sync.aligned.m8n8.x4.shared.b16 {%0,%1,%2,%3}, [%4];"
                 : "=r"(r[0]), "=r"(r[1]), "=r"(r[2]), "=r"(r[3]) : "r"(addr));
}

__device__ __forceinline__ void mma16816(float* c, const uint32_t* a, const uint32_t* b) {
    asm volatile(
        "mma.sync.aligned.m16n8k16.row.col.f32.bf16.bf16.f32 "
        "{%0,%1,%2,%3}, {%4,%5,%6,%7}, {%8,%9}, {%0,%1,%2,%3};"
        : "+f"(c[0]), "+f"(c[1]), "+f"(c[2]), "+f"(c[3])
        : "r"(a[0]), "r"(a[1]), "r"(a[2]), "r"(a[3]), "r"(b[0]), "r"(b[1]));
}

__device__ __forceinline__ void split_bf16(float v, __nv_bfloat16& hi, __nv_bfloat16& lo) {
    hi = __float2bfloat16(v);
    lo = __float2bfloat16(v - __bfloat162float(hi));
}
__device__ __forceinline__ float sigf(float v) { return 1.f / (1.f + expf(-v)); }

// ============================================================
// W conversions
// ============================================================
__global__ void wconv_kernel(const float* __restrict__ w_ih,
                             const float* __restrict__ w_hh) {
    int i = blockIdx.x * 256 + threadIdx.x;    // 0 .. NG*K0-1
    int n = i / K0, c = i - n * K0;
    float v = (c < 2 * CC) ? w_ih[n * (2 * CC) + c] : w_hh[n * CC + (c - 2 * CC)];
    __nv_bfloat16 hi, lo;
    split_bf16(v, hi, lo);
    g_W_hi[i] = hi;
    g_W_lo[i] = lo;
}

// step-1/2 weights: [w_ih[:, :256] + w_hh  |  w_ih[:, 256:512]], K=512
// (valid because q_star = [h | r] for t >= 1)
__global__ void wconv2_kernel(const float* __restrict__ w_ih,
                              const float* __restrict__ w_hh) {
    int i = blockIdx.x * 256 + threadIdx.x;    // 0 .. NG*K1-1
    int n = i >> 9, c = i & 511;
    float v = (c < CC) ? (w_ih[n * (2 * CC) + c] + w_hh[n * CC + c])
                       : w_ih[n * (2 * CC) + c];
    __nv_bfloat16 hi, lo;
    split_bf16(v, hi, lo);
    g_W2_hi[i] = hi;
    g_W2_lo[i] = lo;
}

// q_star input -> A cols [0,512)  (step 0 only)
__global__ void qconv_kernel(const float* __restrict__ q_star) {
    int i = blockIdx.x * 256 + threadIdx.x;    // 0 .. BB*512-1
    int r = i >> 9, c = i & 511;
    __nv_bfloat16 hi, lo;
    split_bf16(q_star[i], hi, lo);
    g_A_hi[r * K0 + c] = hi;
    g_A_lo[r * K0 + c] = lo;
}

// ============================================================
// a_sit + init (cp.async double-buffered, 16-row chunks):
// h = bank_s[b,index] @ x_seg ; c = 0 ; A cols [512,768)
// ============================================================
__global__ void asit_kernel(const float* __restrict__ x,
                            const float* __restrict__ bank_s,
                            const int* __restrict__ index_p) {
    extern __shared__ float xs[];            // 2 * 16*256 floats = 32 KB
    __shared__ float s[LL];
    const int b = blockIdx.x, tid = threadIdx.x;
    int idx = *index_p;
    s[tid] = bank_s[((size_t)b * RR + idx) * LL + tid];

    const float* xb = x + (size_t)b * LL * CC;
    uint32_t sbx = smem_u32(xs);

    auto cp_chunk = [&](int ch) {
        const float* src = xb + (size_t)ch * 16 * CC;
        uint32_t dst = sbx + (ch & 1) * 16384;
#pragma unroll
        for (int i = 0; i < 4; i++)
            CP16(dst + (tid + i * 256) * 16, src + (tid + i * 256) * 4);
    };

    cp_chunk(0);
    CP_COMMIT();

    float acc = 0.f;
    for (int ch = 0; ch < 16; ch++) {
        if (ch + 1 < 16) {
            cp_chunk(ch + 1);
            CP_COMMIT();
            CP_WAIT1();
        } else {
            CP_WAIT0();
        }
        __syncthreads();
        const float* cx = xs + (ch & 1) * 4096;
#pragma unroll
        for (int l = 0; l < 16; l++)
            acc = fmaf(s[ch * 16 + l], cx[l * CC + tid], acc);
        __syncthreads();
    }

    g_h[b * CC + tid] = acc;
    g_c[b * CC + tid] = 0.f;
    __nv_bfloat16 hi, lo;
    split_bf16(acc, hi, lo);
    g_A_hi[b * K0 + 512 + tid] = hi;
    g_A_lo[b * K0 + 512 + tid] = lo;
}

// ============================================================
// bf16x3 tensor-core GEMM via mma.sync, templated on K; buffers
// selected IN DEVICE CODE (compile-time) -- no symbol args from host.
// gates[512,1024] = A[512,K] @ W[1024,K]^T
// CTA tile 64x64, 8 warps (warp tile 32x16, 2m x 4n), K-chunk 64,
// double buffered cp.async. grid (16, 8) = 128 CTAs, 256 threads.
// smem rows padded to 144B (conflict-free ldmatrix).
// ============================================================
#define RSTRIDE 144                   // bytes per 64-elem bf16 row (128 + 16 pad)
#define MAT_BYTES (64 * RSTRIDE)      // 9216 per matrix
#define BUF_BYTES (4 * MAT_BYTES)     // Ah, Al, Wh, Wl = 36864
#define GEMM_SMEM (2 * BUF_BYTES)     // 73728

template <int K>
__global__ __launch_bounds__(256, 1)
void gemm_kernel() {
    constexpr int NC = K / 64;
    const __nv_bfloat16* __restrict__ Ah = (K == K0) ? g_A_hi : g_A2_hi;
    const __nv_bfloat16* __restrict__ Al = (K == K0) ? g_A_lo : g_A2_lo;
    const __nv_bfloat16* __restrict__ Wh = (K == K0) ? g_W_hi : g_W2_hi;
    const __nv_bfloat16* __restrict__ Wl = (K == K0) ? g_W_lo : g_W2_lo;

    extern __shared__ char smem[];
    const uint32_t sb = smem_u32(smem);
    const int tid = threadIdx.x;
    const int lane = tid & 31, wid = tid >> 5;
    const int wm = wid >> 2, wn = wid & 3;        // 2m x 4n warp grid
    const int m0 = blockIdx.y * 64;
    const int n0 = blockIdx.x * 64;

    float acc[2][2][4];
#pragma unroll
    for (int i = 0; i < 2; i++)
#pragma unroll
        for (int j = 0; j < 2; j++)
#pragma unroll
            for (int k = 0; k < 4; k++) acc[i][j][k] = 0.f;

    // per-chunk async copy: each mat 64 rows x 8 x 16B = 512 units;
    // matrix selection fully compile-time (no local pointer array).
    auto cp_chunk = [&](int c) {
        const int k0 = c * 64;
        const uint32_t bo = sb + (c & 1) * BUF_BYTES;
#pragma unroll
        for (int half = 0; half < 2; half++) {
            int u = tid + half * 256;          // 0..511 within each matrix
            int row = u >> 3, cu = u & 7;      // 64 rows x 8 x 16B
            uint32_t doff = bo + row * RSTRIDE + cu * 16;
            size_t aoff = (size_t)(m0 + row) * K + k0 + cu * 8;
            size_t woff = (size_t)(n0 + row) * K + k0 + cu * 8;
            CP16(doff + 0 * MAT_BYTES, Ah + aoff);
            CP16(doff + 1 * MAT_BYTES, Al + aoff);
            CP16(doff + 2 * MAT_BYTES, Wh + woff);
            CP16(doff + 3 * MAT_BYTES, Wl + woff);
        }
    };

    cp_chunk(0);
    CP_COMMIT();

    // ldmatrix lane addressing
    const int a_row = (lane & 15);
    const int a_kb  = (lane >> 4) * 16;
    const int b_row = (lane & 7) + ((lane >> 4) << 3);
    const int b_kb  = ((lane >> 3) & 1) * 16;

    for (int c = 0; c < NC; c++) {
        if (c + 1 < NC) {
            cp_chunk(c + 1);
            CP_COMMIT();
            CP_WAIT1();
        } else {
            CP_WAIT0();
        }
        __syncthreads();

        const uint32_t bo = sb + (c & 1) * BUF_BYTES;
#pragma unroll
        for (int s = 0; s < 4; s++) {               // four k16 steps per chunk
            const int kb = s * 32;
            uint32_t ah[2][4], al[2][4], bh[4], bl[4];
#pragma unroll
            for (int mt = 0; mt < 2; mt++) {
                uint32_t ra = (wm * 32 + mt * 16 + a_row) * RSTRIDE + kb + a_kb;
                ldsm4(ah[mt], bo + 0 * MAT_BYTES + ra);
                ldsm4(al[mt], bo + 1 * MAT_BYTES + ra);
            }
            {
                uint32_t rb = (wn * 16 + b_row) * RSTRIDE + kb + b_kb;
                ldsm4(bh, bo + 2 * MAT_BYTES + rb);
                ldsm4(bl, bo + 3 * MAT_BYTES + rb);
            }
            // term 1: Ah*Wh
#pragma unroll
            for (int mt = 0; mt < 2; mt++)
#pragma unroll
                for (int nf = 0; nf < 2; nf++)
                    mma16816(acc[mt][nf], ah[mt], &bh[nf * 2]);
            // term 2: Ah*Wl
#pragma unroll
            for (int mt = 0; mt < 2; mt++)
#pragma unroll
                for (int nf = 0; nf < 2; nf++)
                    mma16816(acc[mt][nf], ah[mt], &bl[nf * 2]);
            // term 3: Al*Wh
#pragma unroll
            for (int mt = 0; mt < 2; mt++)
#pragma unroll
                for (int nf = 0; nf < 2; nf++)
                    mma16816(acc[mt][nf], al[mt], &bh[nf * 2]);
        }
        __syncthreads();   // WAR vs next cp_chunk into this buffer
    }

    // epilogue
    const int er = lane >> 2, ec = (lane & 3) * 2;
#pragma unroll
    for (int mt = 0; mt < 2; mt++) {
        int row = m0 + wm * 32 + mt * 16 + er;
#pragma unroll
        for (int nf = 0; nf < 2; nf++) {
            int col = n0 + wn * 16 + nf * 8 + ec;
            *(float2*)&g_gates[(size_t)row * NG + col] =
                make_float2(acc[mt][nf][0], acc[mt][nf][1]);
            *(float2*)&g_gates[(size_t)(row + 8) * NG + col] =
                make_float2(acc[mt][nf][2], acc[mt][nf][3]);
        }
    }
}

// ============================================================
// LSTM elementwise; writes h -> g_h, q-half of out, A2 cols [0,256)
// ============================================================
__global__ void lstm_kernel(const float* __restrict__ b_ih,
                            const float* __restrict__ b_hh,
                            float* __restrict__ out) {
    int i = blockIdx.x * 256 + threadIdx.x;
    int b = i >> 8, ch = i & 255;
    const float* gr = g_gates + (size_t)b * NG;
    float ig = gr[ch]        + b_ih[ch]        + b_hh[ch];
    float fg = gr[256 + ch]  + b_ih[256 + ch]  + b_hh[256 + ch];
    float gg = gr[512 + ch]  + b_ih[512 + ch]  + b_hh[512 + ch];
    float og = gr[768 + ch]  + b_ih[768 + ch]  + b_hh[768 + ch];
    float cc = sigf(fg) * g_c[i] + sigf(ig) * tanhf(gg);
    float h  = sigf(og) * tanhf(cc);
    g_c[i] = cc;
    g_h[i] = h;
    out[(size_t)b * (2 * CC) + ch] = h;
    __nv_bfloat16 hi, lo;
    split_bf16(h, hi, lo);
    g_A2_hi[b * K1 + ch] = hi;
    g_A2_lo[b * K1 + ch] = lo;
}

// ============================================================
// Fused segment attention + pooling, online softmax,
// cp.async double-buffered 16-row chunks. Writes r-half + A2 [256,512).
// ============================================================
__global__ void attn_kernel(const float* __restrict__ x, float* __restrict__ out) {
    extern __shared__ float xs[];            // 32 KB
    __shared__ float ebuf[16], pbuf[16];
    const int b = blockIdx.x, tid = threadIdx.x;
    const int lane = tid & 31, w = tid >> 5;

    const float* q = g_h + (size_t)b * CC;
    float qreg[8];
#pragma unroll
    for (int j = 0; j < 8; j++) qreg[j] = q[lane + 32 * j];

    float m = -INFINITY, ssum = 0.f, r = 0.f;
    const float* xb = x + (size_t)b * LL * CC;
    uint32_t sbx = smem_u32(xs);

    auto cp_chunk = [&](int ch) {
        const float* src = xb + (size_t)ch * 16 * CC;
        uint32_t dst = sbx + (ch & 1) * 16384;
#pragma unroll
        for (int i = 0; i < 4; i++)
            CP16(dst + (tid + i * 256) * 16, src + (tid + i * 256) * 4);
    };

    cp_chunk(0);
    CP_COMMIT();

    for (int ch = 0; ch < 16; ch++) {
        if (ch + 1 < 16) {
            cp_chunk(ch + 1);
            CP_COMMIT();
            CP_WAIT1();
        } else {
            CP_WAIT0();
        }
        __syncthreads();
        const float* cx = xs + (ch & 1) * 4096;

#pragma unroll
        for (int jj = 0; jj < 2; jj++) {
            int l = w * 2 + jj;
            const float* row = cx + l * CC;
            float d = 0.f;
#pragma unroll
            for (int j = 0; j < 8; j++) d = fmaf(row[lane + 32 * j], qreg[j], d);
#pragma unroll
            for (int off = 16; off; off >>= 1) d += __shfl_xor_sync(0xffffffffu, d, off);
            if (lane == 0) ebuf[l] = d;
        }
        __syncthreads();

        float cm = ebuf[0];
#pragma unroll
        for (int l = 1; l < 16; l++) cm = fmaxf(cm, ebuf[l]);
        float nm = fmaxf(m, cm);
        if (tid < 16) pbuf[tid] = expf(ebuf[tid] - nm);
        float alpha = expf(m - nm);
        __syncthreads();

        r *= alpha; ssum *= alpha;
        float ps = 0.f;
#pragma unroll
        for (int l = 0; l < 16; l++) {
            float p = pbuf[l];
            r = fmaf(p, cx[l * CC + tid], r);
            ps += p;
        }
        ssum += ps;
        m = nm;
        __syncthreads();
    }

    float rr = r / (ssum + 1e-16f);
    out[(size_t)b * (2 * CC) + CC + tid] = rr;
    __nv_bfloat16 hi, lo;
    split_bf16(rr, hi, lo);
    g_A2_hi[b * K1 + 256 + tid] = hi;
    g_A2_lo[b * K1 + 256 + tid] = lo;
}

// ============================================================
// launch
// ============================================================
extern "C" void kernel_launch(void* const* d_in, const int* in_sizes, int n_in,
                              void* d_out, int out_size) {
    const float* x      = (const float*)d_in[0];
    const float* q_star = (const float*)d_in[2];
    const float* bank_s = (const float*)d_in[3];
    const float* w_ih   = (const float*)d_in[4];
    const float* w_hh   = (const float*)d_in[5];
    const float* b_ih   = (const float*)d_in[6];
    const float* b_hh   = (const float*)d_in[7];
    const int*   index  = (const int*)d_in[8];
    float* out = (float*)d_out;

    cudaFuncSetAttribute(gemm_kernel<K0>, cudaFuncAttributeMaxDynamicSharedMemorySize, GEMM_SMEM);
    cudaFuncSetAttribute(gemm_kernel<K1>, cudaFuncAttributeMaxDynamicSharedMemorySize, GEMM_SMEM);

    wconv_kernel<<<(NG * K0) / 256, 256>>>(w_ih, w_hh);
    wconv2_kernel<<<(NG * K1) / 256, 256>>>(w_ih, w_hh);
    qconv_kernel<<<(BB * 512) / 256, 256>>>(q_star);
    asit_kernel<<<BB, 256, 32768>>>(x, bank_s, index);

    for (int t = 0; t < 3; t++) {
        if (t == 0)
            gemm_kernel<K0><<<dim3(16, 8), 256, GEMM_SMEM>>>();
        else
            gemm_kernel<K1><<<dim3(16, 8), 256, GEMM_SMEM>>>();
        lstm_kernel<<<BB, 256>>>(b_ih, b_hh, out);
        attn_kernel<<<BB, 256, 32768>>>(x, out);
    }
}

// round 13
// speedup vs baseline: 1.6573x; 1.0111x over previous
#include <cuda_runtime.h>
#include <cuda_bf16.h>
#include <math.h>
#include <stdint.h>

#define CC 256     // channels
#define BB 512     // segments
#define LL 256     // nodes per segment
#define RR 8       // bank rows
#define K0 768     // step-0 GEMM K  (512 q_star + 256 h)
#define K1 512     // step-1/2 GEMM K (256 h + 256 r), combined weights
#define NG 1024    // 4*C gate outputs

// ------------------- scratch (device globals) -------------------
// NEVER referenced from host code (host shadow address != device address;
// doing so silently grows a 128MiB HMM pool and trips the alloc guard).
__device__ __align__(128) __nv_bfloat16 g_A_hi[BB * K0];
__device__ __align__(128) __nv_bfloat16 g_A_lo[BB * K0];
__device__ __align__(128) __nv_bfloat16 g_A2_hi[BB * K1];
__device__ __align__(128) __nv_bfloat16 g_A2_lo[BB * K1];
__device__ __align__(128) __nv_bfloat16 g_W_hi[NG * K0];
__device__ __align__(128) __nv_bfloat16 g_W_lo[NG * K0];
__device__ __align__(128) __nv_bfloat16 g_W2_hi[NG * K1];
__device__ __align__(128) __nv_bfloat16 g_W2_lo[NG * K1];
__device__ __align__(128) float g_part0[BB * NG];   // split-K partials
__device__ __align__(128) float g_part1[BB * NG];
__device__ __align__(128) float g_h[BB * CC];
__device__ __align__(128) float g_c[BB * CC];

// ------------------- helpers -------------------
__device__ __forceinline__ uint32_t smem_u32(const void* p) {
    uint32_t a;
    asm("{ .reg .u64 t; cvta.to.shared.u64 t, %1; cvt.u32.u64 %0, t; }" : "=r"(a) : "l"(p));
    return a;
}

#define CP16(dst, src) \
    asm volatile("cp.async.cg.shared.global [%0], [%1], 16;\n" :: "r"(dst), "l"(src))
#define CP_COMMIT() asm volatile("cp.async.commit_group;\n" ::: "memory")
#define CP_WAIT2()  asm volatile("cp.async.wait_group 2;\n" ::: "memory")
#define CP_WAIT1()  asm volatile("cp.async.wait_group 1;\n" ::: "memory")
#define CP_WAIT0()  asm volatile("cp.async.wait_group 0;\n" ::: "memory")

__device__ __forceinline__ void ldsm4(uint32_t* r, uint32_t addr) {
    asm volatile("ldmatrix.sync.aligned.m8n8.x4.shared.b16 {%0,%1,%2,%3}, [%4];"
                 : "=r"(r[0]), "=r"(r[1]), "=r"(r[2]), "=r"(r[3]) : "r"(addr));
}

__device__ __forceinline__ void mma16816(float* c, const uint32_t* a, const uint32_t* b) {
    asm volatile(
        "mma.sync.aligned.m16n8k16.row.col.f32.bf16.bf16.f32 "
        "{%0,%1,%2,%3}, {%4,%5,%6,%7}, {%8,%9}, {%0,%1,%2,%3};"
        : "+f"(c[0]), "+f"(c[1]), "+f"(c[2]), "+f"(c[3])
        : "r"(a[0]), "r"(a[1]), "r"(a[2]), "r"(a[3]), "r"(b[0]), "r"(b[1]));
}

__device__ __forceinline__ void split_bf16(float v, __nv_bfloat16& hi, __nv_bfloat16& lo) {
    hi = __float2bfloat16(v);
    lo = __float2bfloat16(v - __bfloat162float(hi));
}
__device__ __forceinline__ float sigf(float v) { return 1.f / (1.f + expf(-v)); }

// ============================================================
// W conversions
// ============================================================
__global__ void wconv_kernel(const float* __restrict__ w_ih,
                             const float* __restrict__ w_hh) {
    int i = blockIdx.x * 256 + threadIdx.x;    // 0 .. NG*K0-1
    int n = i / K0, c = i - n * K0;
    float v = (c < 2 * CC) ? w_ih[n * (2 * CC) + c] : w_hh[n * CC + (c - 2 * CC)];
    __nv_bfloat16 hi, lo;
    split_bf16(v, hi, lo);
    g_W_hi[i] = hi;
    g_W_lo[i] = lo;
}

// step-1/2 weights: [w_ih[:, :256] + w_hh  |  w_ih[:, 256:512]], K=512
// (valid because q_star = [h | r] for t >= 1)
__global__ void wconv2_kernel(const float* __restrict__ w_ih,
                              const float* __restrict__ w_hh) {
    int i = blockIdx.x * 256 + threadIdx.x;    // 0 .. NG*K1-1
    int n = i >> 9, c = i & 511;
    float v = (c < CC) ? (w_ih[n * (2 * CC) + c] + w_hh[n * CC + c])
                       : w_ih[n * (2 * CC) + c];
    __nv_bfloat16 hi, lo;
    split_bf16(v, hi, lo);
    g_W2_hi[i] = hi;
    g_W2_lo[i] = lo;
}

// q_star input -> A cols [0,512)  (step 0 only)
__global__ void qconv_kernel(const float* __restrict__ q_star) {
    int i = blockIdx.x * 256 + threadIdx.x;    // 0 .. BB*512-1
    int r = i >> 9, c = i & 511;
    __nv_bfloat16 hi, lo;
    split_bf16(q_star[i], hi, lo);
    g_A_hi[r * K0 + c] = hi;
    g_A_lo[r * K0 + c] = lo;
}

// ============================================================
// a_sit + init (cp.async 3-deep pipeline, 16-row chunks):
// h = bank_s[b,index] @ x_seg ; c = 0 ; A cols [512,768)
// ============================================================
__global__ void asit_kernel(const float* __restrict__ x,
                            const float* __restrict__ bank_s,
                            const int* __restrict__ index_p) {
    extern __shared__ float xs[];            // 3 * 16*256 floats = 48 KB
    __shared__ float s[LL];
    const int b = blockIdx.x, tid = threadIdx.x;
    int idx = *index_p;
    s[tid] = bank_s[((size_t)b * RR + idx) * LL + tid];

    const float* xb = x + (size_t)b * LL * CC;
    uint32_t sbx = smem_u32(xs);

    auto cp_chunk = [&](int ch) {
        const float* src = xb + (size_t)ch * 16 * CC;
        uint32_t dst = sbx + (ch % 3) * 16384;
#pragma unroll
        for (int i = 0; i < 4; i++)
            CP16(dst + (tid + i * 256) * 16, src + (tid + i * 256) * 4);
    };

    cp_chunk(0); CP_COMMIT();
    cp_chunk(1); CP_COMMIT();

    float acc = 0.f;
    for (int ch = 0; ch < 16; ch++) {
        if (ch + 2 < 16) {
            cp_chunk(ch + 2);
            CP_COMMIT();
            CP_WAIT2();
        } else if (ch + 1 < 16) {
            CP_WAIT1();
        } else {
            CP_WAIT0();
        }
        __syncthreads();
        const float* cx = xs + (ch % 3) * 4096;
#pragma unroll
        for (int l = 0; l < 16; l++)
            acc = fmaf(s[ch * 16 + l], cx[l * CC + tid], acc);
        __syncthreads();
    }

    g_h[b * CC + tid] = acc;
    g_c[b * CC + tid] = 0.f;
    __nv_bfloat16 hi, lo;
    split_bf16(acc, hi, lo);
    g_A_hi[b * K0 + 512 + tid] = hi;
    g_A_lo[b * K0 + 512 + tid] = lo;
}

// ============================================================
// bf16x3 tensor-core GEMM via mma.sync, templated on K, SPLIT-K x2:
// blockIdx.z selects K-half; partials -> g_part0/g_part1 (deterministic).
// CTA tile 64x64, 8 warps (warp tile 32x16, 2m x 4n), K-chunk 64,
// double buffered cp.async. grid (16, 8, 2) = 256 CTAs, 256 threads.
// Buffers selected IN DEVICE CODE (no symbol args from host).
// ============================================================
#define RSTRIDE 144                   // bytes per 64-elem bf16 row (128 + 16 pad)
#define MAT_BYTES (64 * RSTRIDE)      // 9216 per matrix
#define BUF_BYTES (4 * MAT_BYTES)     // Ah, Al, Wh, Wl = 36864
#define GEMM_SMEM (2 * BUF_BYTES)     // 73728

template <int K>
__global__ __launch_bounds__(256, 1)
void gemm_kernel() {
    constexpr int KH = K / 2;          // per-CTA K
    constexpr int NC = KH / 64;        // chunks (K0: 6, K1: 4)
    const __nv_bfloat16* __restrict__ Ah = (K == K0) ? g_A_hi : g_A2_hi;
    const __nv_bfloat16* __restrict__ Al = (K == K0) ? g_A_lo : g_A2_lo;
    const __nv_bfloat16* __restrict__ Wh = (K == K0) ? g_W_hi : g_W2_hi;
    const __nv_bfloat16* __restrict__ Wl = (K == K0) ? g_W_lo : g_W2_lo;

    extern __shared__ char smem[];
    const uint32_t sb = smem_u32(smem);
    const int tid = threadIdx.x;
    const int lane = tid & 31, wid = tid >> 5;
    const int wm = wid >> 2, wn = wid & 3;        // 2m x 4n warp grid
    const int m0 = blockIdx.y * 64;
    const int n0 = blockIdx.x * 64;
    const int kz = blockIdx.z * KH;               // K-half base

    float acc[2][2][4];
#pragma unroll
    for (int i = 0; i < 2; i++)
#pragma unroll
        for (int j = 0; j < 2; j++)
#pragma unroll
            for (int k = 0; k < 4; k++) acc[i][j][k] = 0.f;

    auto cp_chunk = [&](int c) {
        const int k0 = kz + c * 64;
        const uint32_t bo = sb + (c & 1) * BUF_BYTES;
#pragma unroll
        for (int half = 0; half < 2; half++) {
            int u = tid + half * 256;          // 0..511 within each matrix
            int row = u >> 3, cu = u & 7;      // 64 rows x 8 x 16B
            uint32_t doff = bo + row * RSTRIDE + cu * 16;
            size_t aoff = (size_t)(m0 + row) * K + k0 + cu * 8;
            size_t woff = (size_t)(n0 + row) * K + k0 + cu * 8;
            CP16(doff + 0 * MAT_BYTES, Ah + aoff);
            CP16(doff + 1 * MAT_BYTES, Al + aoff);
            CP16(doff + 2 * MAT_BYTES, Wh + woff);
            CP16(doff + 3 * MAT_BYTES, Wl + woff);
        }
    };

    cp_chunk(0);
    CP_COMMIT();

    // ldmatrix lane addressing
    const int a_row = (lane & 15);
    const int a_kb  = (lane >> 4) * 16;
    const int b_row = (lane & 7) + ((lane >> 4) << 3);
    const int b_kb  = ((lane >> 3) & 1) * 16;

    for (int c = 0; c < NC; c++) {
        if (c + 1 < NC) {
            cp_chunk(c + 1);
            CP_COMMIT();
            CP_WAIT1();
        } else {
            CP_WAIT0();
        }
        __syncthreads();

        const uint32_t bo = sb + (c & 1) * BUF_BYTES;
#pragma unroll
        for (int s = 0; s < 4; s++) {               // four k16 steps per chunk
            const int kb = s * 32;
            uint32_t ah[2][4], al[2][4], bh[4], bl[4];
#pragma unroll
            for (int mt = 0; mt < 2; mt++) {
                uint32_t ra = (wm * 32 + mt * 16 + a_row) * RSTRIDE + kb + a_kb;
                ldsm4(ah[mt], bo + 0 * MAT_BYTES + ra);
                ldsm4(al[mt], bo + 1 * MAT_BYTES + ra);
            }
            {
                uint32_t rb = (wn * 16 + b_row) * RSTRIDE + kb + b_kb;
                ldsm4(bh, bo + 2 * MAT_BYTES + rb);
                ldsm4(bl, bo + 3 * MAT_BYTES + rb);
            }
            // term 1: Ah*Wh
#pragma unroll
            for (int mt = 0; mt < 2; mt++)
#pragma unroll
                for (int nf = 0; nf < 2; nf++)
                    mma16816(acc[mt][nf], ah[mt], &bh[nf * 2]);
            // term 2: Ah*Wl
#pragma unroll
            for (int mt = 0; mt < 2; mt++)
#pragma unroll
                for (int nf = 0; nf < 2; nf++)
                    mma16816(acc[mt][nf], ah[mt], &bl[nf * 2]);
            // term 3: Al*Wh
#pragma unroll
            for (int mt = 0; mt < 2; mt++)
#pragma unroll
                for (int nf = 0; nf < 2; nf++)
                    mma16816(acc[mt][nf], al[mt], &bh[nf * 2]);
        }
        __syncthreads();   // WAR vs next cp_chunk into this buffer
    }

    // epilogue -> split-K partial buffer (device-side selection)
    float* __restrict__ gp = (blockIdx.z == 0) ? g_part0 : g_part1;
    const int er = lane >> 2, ec = (lane & 3) * 2;
#pragma unroll
    for (int mt = 0; mt < 2; mt++) {
        int row = m0 + wm * 32 + mt * 16 + er;
#pragma unroll
        for (int nf = 0; nf < 2; nf++) {
            int col = n0 + wn * 16 + nf * 8 + ec;
            *(float2*)&gp[(size_t)row * NG + col] =
                make_float2(acc[mt][nf][0], acc[mt][nf][1]);
            *(float2*)&gp[(size_t)(row + 8) * NG + col] =
                make_float2(acc[mt][nf][2], acc[mt][nf][3]);
        }
    }
}

// ============================================================
// LSTM elementwise; sums split-K partials + biases.
// Writes h -> g_h, q-half of out, A2 cols [0,256)
// ============================================================
__global__ void lstm_kernel(const float* __restrict__ b_ih,
                            const float* __restrict__ b_hh,
                            float* __restrict__ out) {
    int i = blockIdx.x * 256 + threadIdx.x;
    int b = i >> 8, ch = i & 255;
    size_t base = (size_t)b * NG;
    float ig = g_part0[base + ch]       + g_part1[base + ch]       + b_ih[ch]       + b_hh[ch];
    float fg = g_part0[base + 256 + ch] + g_part1[base + 256 + ch] + b_ih[256 + ch] + b_hh[256 + ch];
    float gg = g_part0[base + 512 + ch] + g_part1[base + 512 + ch] + b_ih[512 + ch] + b_hh[512 + ch];
    float og = g_part0[base + 768 + ch] + g_part1[base + 768 + ch] + b_ih[768 + ch] + b_hh[768 + ch];
    float cc = sigf(fg) * g_c[i] + sigf(ig) * tanhf(gg);
    float h  = sigf(og) * tanhf(cc);
    g_c[i] = cc;
    g_h[i] = h;
    out[(size_t)b * (2 * CC) + ch] = h;
    __nv_bfloat16 hi, lo;
    split_bf16(h, hi, lo);
    g_A2_hi[b * K1 + ch] = hi;
    g_A2_lo[b * K1 + ch] = lo;
}

// ============================================================
// Fused segment attention + pooling, online softmax,
// cp.async 3-deep pipeline, 16-row chunks. Writes r-half + A2 [256,512).
// ============================================================
__global__ void attn_kernel(const float* __restrict__ x, float* __restrict__ out) {
    extern __shared__ float xs[];            // 48 KB (3 buffers)
    __shared__ float ebuf[16], pbuf[16];
    const int b = blockIdx.x, tid = threadIdx.x;
    const int lane = tid & 31, w = tid >> 5;

    const float* q = g_h + (size_t)b * CC;
    float qreg[8];
#pragma unroll
    for (int j = 0; j < 8; j++) qreg[j] = q[lane + 32 * j];

    float m = -INFINITY, ssum = 0.f, r = 0.f;
    const float* xb = x + (size_t)b * LL * CC;
    uint32_t sbx = smem_u32(xs);

    auto cp_chunk = [&](int ch) {
        const float* src = xb + (size_t)ch * 16 * CC;
        uint32_t dst = sbx + (ch % 3) * 16384;
#pragma unroll
        for (int i = 0; i < 4; i++)
            CP16(dst + (tid + i * 256) * 16, src + (tid + i * 256) * 4);
    };

    cp_chunk(0); CP_COMMIT();
    cp_chunk(1); CP_COMMIT();

    for (int ch = 0; ch < 16; ch++) {
        if (ch + 2 < 16) {
            cp_chunk(ch + 2);
            CP_COMMIT();
            CP_WAIT2();
        } else if (ch + 1 < 16) {
            CP_WAIT1();
        } else {
            CP_WAIT0();
        }
        __syncthreads();
        const float* cx = xs + (ch % 3) * 4096;

#pragma unroll
        for (int jj = 0; jj < 2; jj++) {
            int l = w * 2 + jj;
            const float* row = cx + l * CC;
            float d = 0.f;
#pragma unroll
            for (int j = 0; j < 8; j++) d = fmaf(row[lane + 32 * j], qreg[j], d);
#pragma unroll
            for (int off = 16; off; off >>= 1) d += __shfl_xor_sync(0xffffffffu, d, off);
            if (lane == 0) ebuf[l] = d;
        }
        __syncthreads();

        float cm = ebuf[0];
#pragma unroll
        for (int l = 1; l < 16; l++) cm = fmaxf(cm, ebuf[l]);
        float nm = fmaxf(m, cm);
        if (tid < 16) pbuf[tid] = expf(ebuf[tid] - nm);
        float alpha = expf(m - nm);
        __syncthreads();

        r *= alpha; ssum *= alpha;
        float ps = 0.f;
#pragma unroll
        for (int l = 0; l < 16; l++) {
            float p = pbuf[l];
            r = fmaf(p, cx[l * CC + tid], r);
            ps += p;
        }
        ssum += ps;
        m = nm;
        __syncthreads();
    }

    float rr = r / (ssum + 1e-16f);
    out[(size_t)b * (2 * CC) + CC + tid] = rr;
    __nv_bfloat16 hi, lo;
    split_bf16(rr, hi, lo);
    g_A2_hi[b * K1 + 256 + tid] = hi;
    g_A2_lo[b * K1 + 256 + tid] = lo;
}

// ============================================================
// launch
// ============================================================
extern "C" void kernel_launch(void* const* d_in, const int* in_sizes, int n_in,
                              void* d_out, int out_size) {
    const float* x      = (const float*)d_in[0];
    const float* q_star = (const float*)d_in[2];
    const float* bank_s = (const float*)d_in[3];
    const float* w_ih   = (const float*)d_in[4];
    const float* w_hh   = (const float*)d_in[5];
    const float* b_ih   = (const float*)d_in[6];
    const float* b_hh   = (const float*)d_in[7];
    const int*   index  = (const int*)d_in[8];
    float* out = (float*)d_out;

    cudaFuncSetAttribute(gemm_kernel<K0>, cudaFuncAttributeMaxDynamicSharedMemorySize, GEMM_SMEM);
    cudaFuncSetAttribute(gemm_kernel<K1>, cudaFuncAttributeMaxDynamicSharedMemorySize, GEMM_SMEM);
    cudaFuncSetAttribute(asit_kernel, cudaFuncAttributeMaxDynamicSharedMemorySize, 49152);
    cudaFuncSetAttribute(attn_kernel, cudaFuncAttributeMaxDynamicSharedMemorySize, 49152);

    wconv_kernel<<<(NG * K0) / 256, 256>>>(w_ih, w_hh);
    wconv2_kernel<<<(NG * K1) / 256, 256>>>(w_ih, w_hh);
    qconv_kernel<<<(BB * 512) / 256, 256>>>(q_star);
    asit_kernel<<<BB, 256, 49152>>>(x, bank_s, index);

    for (int t = 0; t < 3; t++) {
        if (t == 0)
            gemm_kernel<K0><<<dim3(16, 8, 2), 256, GEMM_SMEM>>>();
        else
            gemm_kernel<K1><<<dim3(16, 8, 2), 256, GEMM_SMEM>>>();
        lstm_kernel<<<BB, 256>>>(b_ih, b_hh, out);
        attn_kernel<<<BB, 256, 49152>>>(x, out);
    }
}